// round 1
// baseline (speedup 1.0000x reference)
#include <cuda_runtime.h>
#include <cstddef>

#define DIM      768
#define NH       12
#define HD       64
#define BB       8
#define SEQ      1024
#define M_TOT    (BB * SEQ)          // 8192
#define QKV_N    (3 * DIM)           // 2304
#define ATT_SCALE 0.125f             // 64^-0.5

// ---------------------------------------------------------------------------
// Scratch (device globals: allocation-free, graph-capturable)
// ---------------------------------------------------------------------------
__device__ float g_qkv[(size_t)M_TOT * QKV_N];   // [8192, 2304]
__device__ float g_att[(size_t)M_TOT * DIM];     // [8192, 768]

// ---------------------------------------------------------------------------
// SGEMM: C[M,N] = A[M,K] * B[N,K]^T (+ bias). 128x128 tile, BK=16,
// 256 threads, 8x8 register tile per thread. All dims divide exactly.
// ---------------------------------------------------------------------------
template<bool BIAS>
__global__ void __launch_bounds__(256, 2)
sgemm_nt(const float* __restrict__ A, const float* __restrict__ B,
         const float* __restrict__ bias, float* __restrict__ C,
         int M, int N, int K)
{
    const int BM = 128, BN = 128, BK = 16;
    __shared__ float As[BK][BM + 4];
    __shared__ float Bs[BK][BN + 4];

    const int tid = threadIdx.x;
    const int tx  = tid & 15;       // 0..15 -> 8 columns each
    const int ty  = tid >> 4;       // 0..15 -> 8 rows each
    const int row0 = blockIdx.y * BM;
    const int col0 = blockIdx.x * BN;

    float acc[8][8];
#pragma unroll
    for (int i = 0; i < 8; i++)
#pragma unroll
        for (int j = 0; j < 8; j++) acc[i][j] = 0.f;

    for (int k0 = 0; k0 < K; k0 += BK) {
        // Load 128x16 tiles of A and B (as [N,K]) transposed into shared.
#pragma unroll
        for (int l = 0; l < 2; l++) {
            int idx = tid + l * 256;        // 0..511 float4 slots
            int r   = idx >> 2;             // row within tile
            int kk  = (idx & 3) << 2;       // k offset (multiple of 4)
            float4 va = *reinterpret_cast<const float4*>(
                &A[(size_t)(row0 + r) * K + k0 + kk]);
            As[kk + 0][r] = va.x; As[kk + 1][r] = va.y;
            As[kk + 2][r] = va.z; As[kk + 3][r] = va.w;
            float4 vb = *reinterpret_cast<const float4*>(
                &B[(size_t)(col0 + r) * K + k0 + kk]);
            Bs[kk + 0][r] = vb.x; Bs[kk + 1][r] = vb.y;
            Bs[kk + 2][r] = vb.z; Bs[kk + 3][r] = vb.w;
        }
        __syncthreads();

#pragma unroll
        for (int kk = 0; kk < BK; kk++) {
            float a[8], b[8];
#pragma unroll
            for (int i = 0; i < 8; i += 4)
                *reinterpret_cast<float4*>(&a[i]) =
                    *reinterpret_cast<const float4*>(&As[kk][ty * 8 + i]);
#pragma unroll
            for (int j = 0; j < 8; j += 4)
                *reinterpret_cast<float4*>(&b[j]) =
                    *reinterpret_cast<const float4*>(&Bs[kk][tx * 8 + j]);
#pragma unroll
            for (int i = 0; i < 8; i++)
#pragma unroll
                for (int j = 0; j < 8; j++)
                    acc[i][j] = fmaf(a[i], b[j], acc[i][j]);
        }
        __syncthreads();
    }

#pragma unroll
    for (int i = 0; i < 8; i++) {
        int r = row0 + ty * 8 + i;
#pragma unroll
        for (int j = 0; j < 8; j += 4) {
            int c = col0 + tx * 8 + j;
            float4 v;
            v.x = acc[i][j + 0]; v.y = acc[i][j + 1];
            v.z = acc[i][j + 2]; v.w = acc[i][j + 3];
            if (BIAS) {
                v.x += bias[c + 0]; v.y += bias[c + 1];
                v.z += bias[c + 2]; v.w += bias[c + 3];
            }
            *reinterpret_cast<float4*>(&C[(size_t)r * N + c]) = v;
        }
    }
}

// ---------------------------------------------------------------------------
// Fused quadratic-ReLU attention.
// One CTA per (q-tile of 128 rows, head, batch). Single pass over KV tiles:
//   S = Q K^T * scale ; P = relu(a*S^2 + b*S + g)
//   rowsum += sum_m P ; O += P V
// Final: O / (rowsum + 1e-6), written to [B, N, H*d] layout for the proj GEMM.
// ---------------------------------------------------------------------------
struct AttnSmem {
    float Qt[HD][128 + 4];       // Q transposed: [e][r]
    float Kt[HD][128 + 4];       // K transposed: [e][c]
    float Vs[128][HD + 4];       // V natural:    [m][e]
    float Ps[128][128 + 4];      // P natural:    [r][m]
    float rs[16][128];           // per-tx partial row sums
    float rowsum[128];           // running row sums
};

extern __shared__ float attn_smem_raw[];

__global__ void __launch_bounds__(256, 1)
attn_kernel(const float* __restrict__ qkv,
            const float* __restrict__ alpha,
            const float* __restrict__ beta,
            const float* __restrict__ gamma,
            float* __restrict__ out)
{
    AttnSmem& s = *reinterpret_cast<AttnSmem*>(attn_smem_raw);
    const int tid = threadIdx.x;
    const int tx  = tid & 15;
    const int ty  = tid >> 4;
    const int qt  = blockIdx.x;      // q tile: 0..7
    const int h   = blockIdx.y;      // head
    const int b   = blockIdx.z;      // batch

    const float av = alpha[h], bv = beta[h], gv = gamma[h];

    const float* qbase = qkv + (size_t)b * SEQ * QKV_N + h * HD;          // s=0
    const float* kbase = qbase + DIM;                                      // s=1
    const float* vbase = qbase + 2 * DIM;                                  // s=2
    const int q0 = qt * 128;

    // Load Q tile [128 x 64] transposed into Qt[e][r]
#pragma unroll
    for (int l = 0; l < 8; l++) {
        int idx = tid + l * 256;         // 0..2047 float4 slots
        int r   = idx >> 4;
        int e   = (idx & 15) << 2;
        float4 v = *reinterpret_cast<const float4*>(
            &qbase[(size_t)(q0 + r) * QKV_N + e]);
        s.Qt[e + 0][r] = v.x; s.Qt[e + 1][r] = v.y;
        s.Qt[e + 2][r] = v.z; s.Qt[e + 3][r] = v.w;
    }
    if (tid < 128) s.rowsum[tid] = 0.f;

    float o[8][4];
#pragma unroll
    for (int i = 0; i < 8; i++)
#pragma unroll
        for (int j = 0; j < 4; j++) o[i][j] = 0.f;

    for (int kt = 0; kt < SEQ / 128; kt++) {
        __syncthreads();   // previous phase-2 done reading Kt/Vs/Ps
        const int m0 = kt * 128;
#pragma unroll
        for (int l = 0; l < 8; l++) {
            int idx = tid + l * 256;
            int r   = idx >> 4;
            int e   = (idx & 15) << 2;
            float4 kv4 = *reinterpret_cast<const float4*>(
                &kbase[(size_t)(m0 + r) * QKV_N + e]);
            s.Kt[e + 0][r] = kv4.x; s.Kt[e + 1][r] = kv4.y;
            s.Kt[e + 2][r] = kv4.z; s.Kt[e + 3][r] = kv4.w;
            float4 vv4 = *reinterpret_cast<const float4*>(
                &vbase[(size_t)(m0 + r) * QKV_N + e]);
            *reinterpret_cast<float4*>(&s.Vs[r][e]) = vv4;
        }
        __syncthreads();

        // ---- Phase 1: S = Q K^T, 8x8 per thread ----
        float sacc[8][8];
#pragma unroll
        for (int i = 0; i < 8; i++)
#pragma unroll
            for (int j = 0; j < 8; j++) sacc[i][j] = 0.f;

#pragma unroll 8
        for (int e = 0; e < HD; e++) {
            float qa[8], kb[8];
#pragma unroll
            for (int i = 0; i < 8; i += 4)
                *reinterpret_cast<float4*>(&qa[i]) =
                    *reinterpret_cast<const float4*>(&s.Qt[e][ty * 8 + i]);
#pragma unroll
            for (int j = 0; j < 8; j += 4)
                *reinterpret_cast<float4*>(&kb[j]) =
                    *reinterpret_cast<const float4*>(&s.Kt[e][tx * 8 + j]);
#pragma unroll
            for (int i = 0; i < 8; i++)
#pragma unroll
                for (int j = 0; j < 8; j++)
                    sacc[i][j] = fmaf(qa[i], kb[j], sacc[i][j]);
        }

        // ---- Apply f(z) = relu(a z^2 + b z + g), stage P, partial row sums ----
#pragma unroll
        for (int i = 0; i < 8; i++) {
            const int r = ty * 8 + i;
            float p[8];
            float rsum = 0.f;
#pragma unroll
            for (int j = 0; j < 8; j++) {
                float z  = sacc[i][j] * ATT_SCALE;
                float pv = fmaf(fmaf(av, z, bv), z, gv);
                pv = fmaxf(pv, 0.f);
                p[j] = pv;
                rsum += pv;
            }
            *reinterpret_cast<float4*>(&s.Ps[r][tx * 8 + 0]) =
                make_float4(p[0], p[1], p[2], p[3]);
            *reinterpret_cast<float4*>(&s.Ps[r][tx * 8 + 4]) =
                make_float4(p[4], p[5], p[6], p[7]);
            s.rs[tx][r] = rsum;
        }
        __syncthreads();

        // Reduce row sums (first 128 threads), others proceed to phase 2.
        if (tid < 128) {
            float t = 0.f;
#pragma unroll
            for (int x = 0; x < 16; x++) t += s.rs[x][tid];
            s.rowsum[tid] += t;
        }

        // ---- Phase 2: O += P V, 8 rows x 4 cols per thread, m unrolled x4 ----
        for (int m = 0; m < 128; m += 4) {
            float pvv[8][4];
#pragma unroll
            for (int i = 0; i < 8; i++) {
                float4 t = *reinterpret_cast<const float4*>(&s.Ps[ty * 8 + i][m]);
                pvv[i][0] = t.x; pvv[i][1] = t.y; pvv[i][2] = t.z; pvv[i][3] = t.w;
            }
            float vvv[4][4];
#pragma unroll
            for (int mm = 0; mm < 4; mm++) {
                float4 t = *reinterpret_cast<const float4*>(&s.Vs[m + mm][tx * 4]);
                vvv[mm][0] = t.x; vvv[mm][1] = t.y; vvv[mm][2] = t.z; vvv[mm][3] = t.w;
            }
#pragma unroll
            for (int i = 0; i < 8; i++)
#pragma unroll
                for (int mm = 0; mm < 4; mm++)
#pragma unroll
                    for (int j = 0; j < 4; j++)
                        o[i][j] = fmaf(pvv[i][mm], vvv[mm][j], o[i][j]);
        }
    }
    __syncthreads();   // rowsum updates visible to all

    // Normalize and write out in [B, N, H*d] (= transpose(0,2,1,3).reshape)
#pragma unroll
    for (int i = 0; i < 8; i++) {
        const int r   = ty * 8 + i;
        const float inv = 1.f / (s.rowsum[r] + 1e-6f);
        float4 v = make_float4(o[i][0] * inv, o[i][1] * inv,
                               o[i][2] * inv, o[i][3] * inv);
        *reinterpret_cast<float4*>(
            &out[(size_t)(b * SEQ + q0 + r) * DIM + h * HD + tx * 4]) = v;
    }
}

// ---------------------------------------------------------------------------
// Launch
// ---------------------------------------------------------------------------
extern "C" void kernel_launch(void* const* d_in, const int* in_sizes, int n_in,
                              void* d_out, int out_size)
{
    const float* x      = (const float*)d_in[0];
    const float* w_qkv  = (const float*)d_in[1];
    const float* w_proj = (const float*)d_in[2];
    const float* b_proj = (const float*)d_in[3];
    const float* alpha  = (const float*)d_in[4];
    const float* beta   = (const float*)d_in[5];
    const float* gamma  = (const float*)d_in[6];
    float* out = (float*)d_out;

    float* qkv = nullptr;
    float* att = nullptr;
    cudaGetSymbolAddress((void**)&qkv, g_qkv);
    cudaGetSymbolAddress((void**)&att, g_att);

    const size_t attn_smem = sizeof(AttnSmem);
    cudaFuncSetAttribute(attn_kernel,
                         cudaFuncAttributeMaxDynamicSharedMemorySize,
                         (int)attn_smem);

    // 1) QKV projection: [8192,768] x [2304,768]^T -> [8192,2304]
    {
        dim3 grid(QKV_N / 128, M_TOT / 128);
        sgemm_nt<false><<<grid, 256>>>(x, w_qkv, nullptr, qkv,
                                       M_TOT, QKV_N, DIM);
    }

    // 2) Fused quadratic attention -> [8192,768] in [B,N,H*d] layout
    {
        dim3 grid(SEQ / 128, NH, BB);
        attn_kernel<<<grid, 256, attn_smem>>>(qkv, alpha, beta, gamma, att);
    }

    // 3) Output projection + bias: [8192,768] x [768,768]^T -> [8192,768]
    {
        dim3 grid(DIM / 128, M_TOT / 128);
        sgemm_nt<true><<<grid, 256>>>(att, w_proj, b_proj, out,
                                      M_TOT, DIM, DIM);
    }
}

// round 2
// speedup vs baseline: 2.3418x; 2.3418x over previous
#include <cuda_runtime.h>
#include <cuda_bf16.h>
#include <cstdint>
#include <cstddef>

#define DIM      768
#define NH       12
#define HD       64
#define BB       8
#define SEQ      1024
#define M_TOT    (BB * SEQ)          // 8192
#define QKV_N    (3 * DIM)           // 2304
#define ATT_SCALE 0.125f

// ---------------------------------------------------------------------------
// Scratch planes (bf16 hi/lo splits). Device globals: allocation-free.
// ---------------------------------------------------------------------------
__device__ __nv_bfloat16 g_x_hi[(size_t)M_TOT * DIM];
__device__ __nv_bfloat16 g_x_lo[(size_t)M_TOT * DIM];
__device__ __nv_bfloat16 g_wqkv_hi[(size_t)QKV_N * DIM];
__device__ __nv_bfloat16 g_wqkv_lo[(size_t)QKV_N * DIM];
__device__ __nv_bfloat16 g_wproj_hi[(size_t)DIM * DIM];
__device__ __nv_bfloat16 g_wproj_lo[(size_t)DIM * DIM];
__device__ __nv_bfloat16 g_qkv_hi[(size_t)M_TOT * QKV_N];
__device__ __nv_bfloat16 g_qkv_lo[(size_t)M_TOT * QKV_N];
__device__ __nv_bfloat16 g_att_hi[(size_t)M_TOT * DIM];
__device__ __nv_bfloat16 g_att_lo[(size_t)M_TOT * DIM];

// ---------------------------------------------------------------------------
// Small helpers
// ---------------------------------------------------------------------------
__device__ __forceinline__ uint32_t sptr(const void* p) {
    return (uint32_t)__cvta_generic_to_shared(p);
}

__device__ __forceinline__ void ldsm4(uint32_t r[4], uint32_t a) {
    asm volatile("ldmatrix.sync.aligned.m8n8.x4.shared.b16 {%0,%1,%2,%3}, [%4];"
                 : "=r"(r[0]), "=r"(r[1]), "=r"(r[2]), "=r"(r[3]) : "r"(a));
}
__device__ __forceinline__ void ldsm4t(uint32_t r[4], uint32_t a) {
    asm volatile("ldmatrix.sync.aligned.m8n8.x4.trans.shared.b16 {%0,%1,%2,%3}, [%4];"
                 : "=r"(r[0]), "=r"(r[1]), "=r"(r[2]), "=r"(r[3]) : "r"(a));
}
__device__ __forceinline__ void mma_bf16(float c[4], const uint32_t a[4],
                                         uint32_t b0, uint32_t b1) {
    asm volatile(
        "mma.sync.aligned.m16n8k16.row.col.f32.bf16.bf16.f32 "
        "{%0,%1,%2,%3},{%4,%5,%6,%7},{%8,%9},{%0,%1,%2,%3};"
        : "+f"(c[0]), "+f"(c[1]), "+f"(c[2]), "+f"(c[3])
        : "r"(a[0]), "r"(a[1]), "r"(a[2]), "r"(a[3]), "r"(b0), "r"(b1));
}

// pack (low element, high element) into one 32-bit bf16x2 word
__device__ __forceinline__ uint32_t packbf(float e0, float e1) {
    unsigned short l = __bfloat16_as_ushort(__float2bfloat16_rn(e0));
    unsigned short h = __bfloat16_as_ushort(__float2bfloat16_rn(e1));
    return (uint32_t)l | ((uint32_t)h << 16);
}
__device__ __forceinline__ void split_pair(float x, float y,
                                           uint32_t& hi, uint32_t& lo) {
    __nv_bfloat16 bx = __float2bfloat16_rn(x);
    __nv_bfloat16 by = __float2bfloat16_rn(y);
    hi = (uint32_t)__bfloat16_as_ushort(bx) |
         ((uint32_t)__bfloat16_as_ushort(by) << 16);
    lo = packbf(x - __bfloat162float(bx), y - __bfloat162float(by));
}

// ---------------------------------------------------------------------------
// fp32 -> bf16 hi/lo plane conversion
// ---------------------------------------------------------------------------
__global__ void split_planes(const float4* __restrict__ in,
                             uint2* __restrict__ hi, uint2* __restrict__ lo,
                             int n4) {
    int i = blockIdx.x * blockDim.x + threadIdx.x;
    if (i >= n4) return;
    float4 v = in[i];
    uint32_t h0, l0, h1, l1;
    split_pair(v.x, v.y, h0, l0);
    split_pair(v.z, v.w, h1, l1);
    hi[i] = make_uint2(h0, h1);
    lo[i] = make_uint2(l0, l1);
}

// ---------------------------------------------------------------------------
// Split-bf16 tensor-core GEMM: C[M,N] = A[M,K] * B[N,K]^T
// A,B given as hi/lo bf16 planes. 128x128 CTA tile, BK=32, 8 warps (2m x 4n),
// each warp 64x32 via m16n8k16. 3 MMAs per logical product (hi*hi+hi*lo+lo*hi).
// SPLIT_OUT: write C as hi/lo bf16 planes; else fp32 + bias.
// ---------------------------------------------------------------------------
template<bool SPLIT_OUT>
__global__ void __launch_bounds__(256, 2)
gemm_bf16s(const __nv_bfloat16* __restrict__ Ah_g,
           const __nv_bfloat16* __restrict__ Al_g,
           const __nv_bfloat16* __restrict__ Bh_g,
           const __nv_bfloat16* __restrict__ Bl_g,
           const float* __restrict__ bias,
           __nv_bfloat16* __restrict__ Ch,
           __nv_bfloat16* __restrict__ Cl,
           float* __restrict__ Cf,
           int M, int N, int K)
{
    __shared__ __nv_bfloat16 Ah[128][40], Al[128][40];
    __shared__ __nv_bfloat16 Bh[128][40], Bl[128][40];

    const int tid  = threadIdx.x;
    const int lane = tid & 31;
    const int w    = tid >> 5;
    const int wm   = w & 1;       // 2 m-groups of 64
    const int wn   = w >> 1;      // 4 n-groups of 32
    const int row0 = blockIdx.y * 128;
    const int col0 = blockIdx.x * 128;

    float acc[4][4][4];
#pragma unroll
    for (int a = 0; a < 4; a++)
#pragma unroll
        for (int b = 0; b < 4; b++)
#pragma unroll
            for (int c = 0; c < 4; c++) acc[a][b][c] = 0.f;

    for (int k0 = 0; k0 < K; k0 += 32) {
#pragma unroll
        for (int l = 0; l < 2; l++) {
            int idx = tid + 256 * l;        // 0..511
            int r = idx >> 2, p = idx & 3;  // row, float4-slot
            *reinterpret_cast<float4*>(&Ah[r][p * 8]) =
                *reinterpret_cast<const float4*>(&Ah_g[(size_t)(row0 + r) * K + k0 + p * 8]);
            *reinterpret_cast<float4*>(&Al[r][p * 8]) =
                *reinterpret_cast<const float4*>(&Al_g[(size_t)(row0 + r) * K + k0 + p * 8]);
            *reinterpret_cast<float4*>(&Bh[r][p * 8]) =
                *reinterpret_cast<const float4*>(&Bh_g[(size_t)(col0 + r) * K + k0 + p * 8]);
            *reinterpret_cast<float4*>(&Bl[r][p * 8]) =
                *reinterpret_cast<const float4*>(&Bl_g[(size_t)(col0 + r) * K + k0 + p * 8]);
        }
        __syncthreads();

#pragma unroll
        for (int kk = 0; kk < 32; kk += 16) {
            uint32_t ah[4][4], al[4][4];
#pragma unroll
            for (int mt = 0; mt < 4; mt++) {
                int r = 64 * wm + 16 * mt + (lane & 15);
                int c = kk + (lane >> 4) * 8;
                ldsm4(ah[mt], sptr(&Ah[r][c]));
                ldsm4(al[mt], sptr(&Al[r][c]));
            }
#pragma unroll
            for (int np = 0; np < 2; np++) {
                uint32_t bh[4], bl[4];
                int r = 32 * wn + 16 * np + (lane & 7) + (lane >> 4) * 8;
                int c = kk + ((lane >> 3) & 1) * 8;
                ldsm4(bh, sptr(&Bh[r][c]));
                ldsm4(bl, sptr(&Bl[r][c]));
#pragma unroll
                for (int mt = 0; mt < 4; mt++) {
#pragma unroll
                    for (int h2 = 0; h2 < 2; h2++) {
                        float* cc = acc[mt][2 * np + h2];
                        mma_bf16(cc, ah[mt], bh[2 * h2], bh[2 * h2 + 1]);
                        mma_bf16(cc, ah[mt], bl[2 * h2], bl[2 * h2 + 1]);
                        mma_bf16(cc, al[mt], bh[2 * h2], bh[2 * h2 + 1]);
                    }
                }
            }
        }
        __syncthreads();
    }

    // Epilogue
#pragma unroll
    for (int mt = 0; mt < 4; mt++) {
#pragma unroll
        for (int nt = 0; nt < 4; nt++) {
            int gr = row0 + 64 * wm + 16 * mt + (lane >> 2);
            int gc = col0 + 32 * wn + 8 * nt + 2 * (lane & 3);
            const float* cc = acc[mt][nt];
            if (SPLIT_OUT) {
                uint32_t h, l;
                split_pair(cc[0], cc[1], h, l);
                *reinterpret_cast<uint32_t*>(&Ch[(size_t)gr * N + gc]) = h;
                *reinterpret_cast<uint32_t*>(&Cl[(size_t)gr * N + gc]) = l;
                split_pair(cc[2], cc[3], h, l);
                *reinterpret_cast<uint32_t*>(&Ch[(size_t)(gr + 8) * N + gc]) = h;
                *reinterpret_cast<uint32_t*>(&Cl[(size_t)(gr + 8) * N + gc]) = l;
            } else {
                float b0 = bias[gc], b1 = bias[gc + 1];
                *reinterpret_cast<float2*>(&Cf[(size_t)gr * N + gc]) =
                    make_float2(cc[0] + b0, cc[1] + b1);
                *reinterpret_cast<float2*>(&Cf[(size_t)(gr + 8) * N + gc]) =
                    make_float2(cc[2] + b0, cc[3] + b1);
            }
        }
    }
}

// ---------------------------------------------------------------------------
// Fused quadratic-ReLU attention, tensor-core version.
// CTA = (q-tile 128, head, batch); 8 warps, warp w owns q rows 16w..16w+15.
// Per key tile of 128: S = QK^T (split-bf16 mma), f(z) in registers,
// P fragments rebuilt in registers (C-frag layout == A-frag layout),
// O += P V via ldmatrix.trans on naturally laid-out V. Row sums via shfl.
// ---------------------------------------------------------------------------
struct AttnSmem {
    __nv_bfloat16 Qh[128][72], Ql[128][72];
    __nv_bfloat16 Kh[128][72], Kl[128][72];
    __nv_bfloat16 Vh[128][72], Vl[128][72];
};
extern __shared__ char attn_smem_raw[];

__device__ __forceinline__ void load_tile72(__nv_bfloat16 (*dst)[72],
                                            const __nv_bfloat16* __restrict__ src,
                                            int tid) {
#pragma unroll
    for (int l = 0; l < 4; l++) {
        int idx = tid + 256 * l;      // 0..1023 float4 slots
        int r = idx >> 3, p = idx & 7;
        *reinterpret_cast<float4*>(&dst[r][p * 8]) =
            *reinterpret_cast<const float4*>(&src[(size_t)r * QKV_N + p * 8]);
    }
}

__global__ void __launch_bounds__(256, 1)
attn_mma(const __nv_bfloat16* __restrict__ qkv_hi,
         const __nv_bfloat16* __restrict__ qkv_lo,
         const float* __restrict__ alpha,
         const float* __restrict__ beta,
         const float* __restrict__ gamma,
         __nv_bfloat16* __restrict__ att_hi,
         __nv_bfloat16* __restrict__ att_lo)
{
    AttnSmem& s = *reinterpret_cast<AttnSmem*>(attn_smem_raw);
    const int tid  = threadIdx.x;
    const int lane = tid & 31;
    const int w    = tid >> 5;
    const int qt   = blockIdx.x;
    const int h    = blockIdx.y;
    const int b    = blockIdx.z;
    const int q0   = qt * 128;

    const float av = alpha[h], bv = beta[h], gv = gamma[h];

    const size_t base = (size_t)(b * SEQ) * QKV_N + h * HD;
    const __nv_bfloat16* qh_g = qkv_hi + base + (size_t)q0 * QKV_N;
    const __nv_bfloat16* ql_g = qkv_lo + base + (size_t)q0 * QKV_N;

    load_tile72(s.Qh, qh_g, tid);
    load_tile72(s.Ql, ql_g, tid);
    __syncthreads();

    // Q fragments (persist across key tiles)
    uint32_t qh[4][4], ql[4][4];
#pragma unroll
    for (int kc = 0; kc < 4; kc++) {
        int r = 16 * w + (lane & 15);
        int c = 16 * kc + (lane >> 4) * 8;
        ldsm4(qh[kc], sptr(&s.Qh[r][c]));
        ldsm4(ql[kc], sptr(&s.Ql[r][c]));
    }

    float O[8][4];
#pragma unroll
    for (int j = 0; j < 8; j++)
#pragma unroll
        for (int q = 0; q < 4; q++) O[j][q] = 0.f;
    float rsum0 = 0.f, rsum1 = 0.f;

    for (int kt = 0; kt < SEQ / 128; kt++) {
        __syncthreads();   // previous iteration done reading K/V
        const size_t koff = base + (size_t)(kt * 128) * QKV_N;
        load_tile72(s.Kh, qkv_hi + koff + DIM,     tid);
        load_tile72(s.Kl, qkv_lo + koff + DIM,     tid);
        load_tile72(s.Vh, qkv_hi + koff + 2 * DIM, tid);
        load_tile72(s.Vl, qkv_lo + koff + 2 * DIM, tid);
        __syncthreads();

        // ---- Phase 1: S = Q K^T ----
        float S[16][4];
#pragma unroll
        for (int j = 0; j < 16; j++)
#pragma unroll
            for (int q = 0; q < 4; q++) S[j][q] = 0.f;

#pragma unroll
        for (int kc = 0; kc < 4; kc++) {
#pragma unroll
            for (int np = 0; np < 8; np++) {
                uint32_t kh[4], kl[4];
                int r = 16 * np + (lane & 7) + (lane >> 4) * 8;
                int c = 16 * kc + ((lane >> 3) & 1) * 8;
                ldsm4(kh, sptr(&s.Kh[r][c]));
                ldsm4(kl, sptr(&s.Kl[r][c]));
                mma_bf16(S[2 * np + 0], qh[kc], kh[0], kh[1]);
                mma_bf16(S[2 * np + 0], qh[kc], kl[0], kl[1]);
                mma_bf16(S[2 * np + 0], ql[kc], kh[0], kh[1]);
                mma_bf16(S[2 * np + 1], qh[kc], kh[2], kh[3]);
                mma_bf16(S[2 * np + 1], qh[kc], kl[2], kl[3]);
                mma_bf16(S[2 * np + 1], ql[kc], kh[2], kh[3]);
            }
        }

        // ---- f(z) = relu(a z^2 + b z + g), row-sum partials ----
#pragma unroll
        for (int j = 0; j < 16; j++) {
#pragma unroll
            for (int q = 0; q < 4; q++) {
                float z = S[j][q] * ATT_SCALE;
                float p = fmaf(fmaf(av, z, bv), z, gv);
                p = fmaxf(p, 0.f);
                S[j][q] = p;
            }
            rsum0 += S[j][0] + S[j][1];
            rsum1 += S[j][2] + S[j][3];
        }

        // ---- Phase 2: O += P V ----
#pragma unroll
        for (int c8 = 0; c8 < 8; c8++) {
            uint32_t ph[4], pl[4];
            split_pair(S[2 * c8][0],     S[2 * c8][1],     ph[0], pl[0]);
            split_pair(S[2 * c8][2],     S[2 * c8][3],     ph[1], pl[1]);
            split_pair(S[2 * c8 + 1][0], S[2 * c8 + 1][1], ph[2], pl[2]);
            split_pair(S[2 * c8 + 1][2], S[2 * c8 + 1][3], ph[3], pl[3]);
#pragma unroll
            for (int ep = 0; ep < 4; ep++) {
                uint32_t vh[4], vl[4];
                int r = 16 * c8 + (lane & 7) + ((lane >> 3) & 1) * 8;
                int c = 16 * ep + (lane >> 4) * 8;
                ldsm4t(vh, sptr(&s.Vh[r][c]));
                ldsm4t(vl, sptr(&s.Vl[r][c]));
                mma_bf16(O[2 * ep + 0], ph, vh[0], vh[1]);
                mma_bf16(O[2 * ep + 0], ph, vl[0], vl[1]);
                mma_bf16(O[2 * ep + 0], pl, vh[0], vh[1]);
                mma_bf16(O[2 * ep + 1], ph, vh[2], vh[3]);
                mma_bf16(O[2 * ep + 1], ph, vl[2], vl[3]);
                mma_bf16(O[2 * ep + 1], pl, vh[2], vh[3]);
            }
        }
    }

    // Row sums: reduce across the 4 lanes sharing each row
    rsum0 += __shfl_xor_sync(0xffffffffu, rsum0, 1);
    rsum0 += __shfl_xor_sync(0xffffffffu, rsum0, 2);
    rsum1 += __shfl_xor_sync(0xffffffffu, rsum1, 1);
    rsum1 += __shfl_xor_sync(0xffffffffu, rsum1, 2);
    const float inv0 = 1.f / (rsum0 + 1e-6f);
    const float inv1 = 1.f / (rsum1 + 1e-6f);

    // Epilogue: write hi/lo planes of att in [B, N, H*d]
    const int r0 = b * SEQ + q0 + 16 * w + (lane >> 2);
#pragma unroll
    for (int j = 0; j < 8; j++) {
        int ce = h * HD + 8 * j + 2 * (lane & 3);
        uint32_t hh, ll;
        split_pair(O[j][0] * inv0, O[j][1] * inv0, hh, ll);
        *reinterpret_cast<uint32_t*>(&att_hi[(size_t)r0 * DIM + ce]) = hh;
        *reinterpret_cast<uint32_t*>(&att_lo[(size_t)r0 * DIM + ce]) = ll;
        split_pair(O[j][2] * inv1, O[j][3] * inv1, hh, ll);
        *reinterpret_cast<uint32_t*>(&att_hi[(size_t)(r0 + 8) * DIM + ce]) = hh;
        *reinterpret_cast<uint32_t*>(&att_lo[(size_t)(r0 + 8) * DIM + ce]) = ll;
    }
}

// ---------------------------------------------------------------------------
// Launch
// ---------------------------------------------------------------------------
extern "C" void kernel_launch(void* const* d_in, const int* in_sizes, int n_in,
                              void* d_out, int out_size)
{
    const float* x      = (const float*)d_in[0];
    const float* w_qkv  = (const float*)d_in[1];
    const float* w_proj = (const float*)d_in[2];
    const float* b_proj = (const float*)d_in[3];
    const float* alpha  = (const float*)d_in[4];
    const float* beta   = (const float*)d_in[5];
    const float* gamma  = (const float*)d_in[6];
    float* out = (float*)d_out;

    __nv_bfloat16 *xh, *xl, *wqh, *wql, *wph, *wpl, *qh, *ql, *ah, *al;
    cudaGetSymbolAddress((void**)&xh,  g_x_hi);
    cudaGetSymbolAddress((void**)&xl,  g_x_lo);
    cudaGetSymbolAddress((void**)&wqh, g_wqkv_hi);
    cudaGetSymbolAddress((void**)&wql, g_wqkv_lo);
    cudaGetSymbolAddress((void**)&wph, g_wproj_hi);
    cudaGetSymbolAddress((void**)&wpl, g_wproj_lo);
    cudaGetSymbolAddress((void**)&qh,  g_qkv_hi);
    cudaGetSymbolAddress((void**)&ql,  g_qkv_lo);
    cudaGetSymbolAddress((void**)&ah,  g_att_hi);
    cudaGetSymbolAddress((void**)&al,  g_att_lo);

    cudaFuncSetAttribute(attn_mma,
                         cudaFuncAttributeMaxDynamicSharedMemorySize,
                         (int)sizeof(AttnSmem));

    // 0) split fp32 inputs into bf16 hi/lo planes
    {
        int n4 = M_TOT * DIM / 4;
        split_planes<<<(n4 + 255) / 256, 256>>>((const float4*)x, (uint2*)xh, (uint2*)xl, n4);
        n4 = QKV_N * DIM / 4;
        split_planes<<<(n4 + 255) / 256, 256>>>((const float4*)w_qkv, (uint2*)wqh, (uint2*)wql, n4);
        n4 = DIM * DIM / 4;
        split_planes<<<(n4 + 255) / 256, 256>>>((const float4*)w_proj, (uint2*)wph, (uint2*)wpl, n4);
    }

    // 1) QKV projection -> split planes
    {
        dim3 grid(QKV_N / 128, M_TOT / 128);
        gemm_bf16s<true><<<grid, 256>>>(xh, xl, wqh, wql, nullptr,
                                        qh, ql, nullptr, M_TOT, QKV_N, DIM);
    }

    // 2) Fused quadratic attention -> split planes
    {
        dim3 grid(SEQ / 128, NH, BB);
        attn_mma<<<grid, 256, sizeof(AttnSmem)>>>(qh, ql, alpha, beta, gamma, ah, al);
    }

    // 3) Output projection + bias -> fp32 out
    {
        dim3 grid(DIM / 128, M_TOT / 128);
        gemm_bf16s<false><<<grid, 256>>>(ah, al, wph, wpl, b_proj,
                                         nullptr, nullptr, out, M_TOT, DIM, DIM);
    }
}

// round 3
// speedup vs baseline: 2.5680x; 1.0966x over previous
#include <cuda_runtime.h>
#include <cuda_bf16.h>
#include <cstdint>
#include <cstddef>

#define DIM      768
#define NH       12
#define HD       64
#define BB       8
#define SEQ      1024
#define M_TOT    (BB * SEQ)          // 8192
#define QKV_N    (3 * DIM)           // 2304
#define ATT_SCALE 0.125f

// ---------------------------------------------------------------------------
// Scratch planes (bf16 hi/lo splits). Device globals: allocation-free.
// ---------------------------------------------------------------------------
__device__ __nv_bfloat16 g_x_hi[(size_t)M_TOT * DIM];
__device__ __nv_bfloat16 g_x_lo[(size_t)M_TOT * DIM];
__device__ __nv_bfloat16 g_wqkv_hi[(size_t)QKV_N * DIM];
__device__ __nv_bfloat16 g_wqkv_lo[(size_t)QKV_N * DIM];
__device__ __nv_bfloat16 g_wproj_hi[(size_t)DIM * DIM];
__device__ __nv_bfloat16 g_wproj_lo[(size_t)DIM * DIM];
__device__ __nv_bfloat16 g_qkv_hi[(size_t)M_TOT * QKV_N];
__device__ __nv_bfloat16 g_qkv_lo[(size_t)M_TOT * QKV_N];
__device__ __nv_bfloat16 g_att_hi[(size_t)M_TOT * DIM];
__device__ __nv_bfloat16 g_att_lo[(size_t)M_TOT * DIM];

// ---------------------------------------------------------------------------
// Small helpers
// ---------------------------------------------------------------------------
__device__ __forceinline__ uint32_t sptr(const void* p) {
    return (uint32_t)__cvta_generic_to_shared(p);
}

__device__ __forceinline__ void cp16(void* dst, const void* src) {
    asm volatile("cp.async.cg.shared.global [%0], [%1], 16;"
                 :: "r"(sptr(dst)), "l"(src));
}
__device__ __forceinline__ void cp_commit() {
    asm volatile("cp.async.commit_group;");
}
template<int N>
__device__ __forceinline__ void cp_wait() {
    asm volatile("cp.async.wait_group %0;" :: "n"(N));
}

__device__ __forceinline__ void ldsm4(uint32_t r[4], uint32_t a) {
    asm volatile("ldmatrix.sync.aligned.m8n8.x4.shared.b16 {%0,%1,%2,%3}, [%4];"
                 : "=r"(r[0]), "=r"(r[1]), "=r"(r[2]), "=r"(r[3]) : "r"(a));
}
__device__ __forceinline__ void ldsm4t(uint32_t r[4], uint32_t a) {
    asm volatile("ldmatrix.sync.aligned.m8n8.x4.trans.shared.b16 {%0,%1,%2,%3}, [%4];"
                 : "=r"(r[0]), "=r"(r[1]), "=r"(r[2]), "=r"(r[3]) : "r"(a));
}
__device__ __forceinline__ void mma_bf16(float c[4], const uint32_t a[4],
                                         uint32_t b0, uint32_t b1) {
    asm volatile(
        "mma.sync.aligned.m16n8k16.row.col.f32.bf16.bf16.f32 "
        "{%0,%1,%2,%3},{%4,%5,%6,%7},{%8,%9},{%0,%1,%2,%3};"
        : "+f"(c[0]), "+f"(c[1]), "+f"(c[2]), "+f"(c[3])
        : "r"(a[0]), "r"(a[1]), "r"(a[2]), "r"(a[3]), "r"(b0), "r"(b1));
}

__device__ __forceinline__ uint32_t packbf(float e0, float e1) {
    unsigned short l = __bfloat16_as_ushort(__float2bfloat16_rn(e0));
    unsigned short h = __bfloat16_as_ushort(__float2bfloat16_rn(e1));
    return (uint32_t)l | ((uint32_t)h << 16);
}
__device__ __forceinline__ void split_pair(float x, float y,
                                           uint32_t& hi, uint32_t& lo) {
    __nv_bfloat16 bx = __float2bfloat16_rn(x);
    __nv_bfloat16 by = __float2bfloat16_rn(y);
    hi = (uint32_t)__bfloat16_as_ushort(bx) |
         ((uint32_t)__bfloat16_as_ushort(by) << 16);
    lo = packbf(x - __bfloat162float(bx), y - __bfloat162float(by));
}

// ---------------------------------------------------------------------------
// fp32 -> bf16 hi/lo plane conversion
// ---------------------------------------------------------------------------
__global__ void split_planes(const float4* __restrict__ in,
                             uint2* __restrict__ hi, uint2* __restrict__ lo,
                             int n4) {
    int i = blockIdx.x * blockDim.x + threadIdx.x;
    if (i >= n4) return;
    float4 v = in[i];
    uint32_t h0, l0, h1, l1;
    split_pair(v.x, v.y, h0, l0);
    split_pair(v.z, v.w, h1, l1);
    hi[i] = make_uint2(h0, h1);
    lo[i] = make_uint2(l0, l1);
}

// ---------------------------------------------------------------------------
// Split-bf16 tensor-core GEMM with cp.async 2-stage pipeline.
// C[M,N] = A[M,K] * B[N,K]^T. 128x128 CTA tile, BK=32, 8 warps (2m x 4n).
// ---------------------------------------------------------------------------
struct GemmSmem {
    __nv_bfloat16 Ah[2][128][40], Al[2][128][40];
    __nv_bfloat16 Bh[2][128][40], Bl[2][128][40];
};
extern __shared__ char smem_raw[];

__device__ __forceinline__ void gemm_load_stage(
    GemmSmem& s, int st,
    const __nv_bfloat16* __restrict__ Ah_g, const __nv_bfloat16* __restrict__ Al_g,
    const __nv_bfloat16* __restrict__ Bh_g, const __nv_bfloat16* __restrict__ Bl_g,
    int row0, int col0, int K, int k0, int tid)
{
#pragma unroll
    for (int l = 0; l < 2; l++) {
        int idx = tid + 256 * l;        // 0..511
        int r = idx >> 2, p = idx & 3;  // row, 16B slot
        cp16(&s.Ah[st][r][p * 8], &Ah_g[(size_t)(row0 + r) * K + k0 + p * 8]);
        cp16(&s.Al[st][r][p * 8], &Al_g[(size_t)(row0 + r) * K + k0 + p * 8]);
        cp16(&s.Bh[st][r][p * 8], &Bh_g[(size_t)(col0 + r) * K + k0 + p * 8]);
        cp16(&s.Bl[st][r][p * 8], &Bl_g[(size_t)(col0 + r) * K + k0 + p * 8]);
    }
}

template<bool SPLIT_OUT>
__global__ void __launch_bounds__(256, 2)
gemm_bf16s(const __nv_bfloat16* __restrict__ Ah_g,
           const __nv_bfloat16* __restrict__ Al_g,
           const __nv_bfloat16* __restrict__ Bh_g,
           const __nv_bfloat16* __restrict__ Bl_g,
           const float* __restrict__ bias,
           __nv_bfloat16* __restrict__ Ch,
           __nv_bfloat16* __restrict__ Cl,
           float* __restrict__ Cf,
           int M, int N, int K)
{
    GemmSmem& s = *reinterpret_cast<GemmSmem*>(smem_raw);

    const int tid  = threadIdx.x;
    const int lane = tid & 31;
    const int w    = tid >> 5;
    const int wm   = w & 1;
    const int wn   = w >> 1;
    const int row0 = blockIdx.y * 128;
    const int col0 = blockIdx.x * 128;

    float acc[4][4][4];
#pragma unroll
    for (int a = 0; a < 4; a++)
#pragma unroll
        for (int b = 0; b < 4; b++)
#pragma unroll
            for (int c = 0; c < 4; c++) acc[a][b][c] = 0.f;

    const int nk = K / 32;
    gemm_load_stage(s, 0, Ah_g, Al_g, Bh_g, Bl_g, row0, col0, K, 0, tid);
    cp_commit();

    for (int i = 0; i < nk; i++) {
        const int st = i & 1;
        if (i + 1 < nk) {
            gemm_load_stage(s, st ^ 1, Ah_g, Al_g, Bh_g, Bl_g,
                            row0, col0, K, (i + 1) * 32, tid);
            cp_commit();
            cp_wait<1>();
        } else {
            cp_wait<0>();
        }
        __syncthreads();

#pragma unroll
        for (int kk = 0; kk < 32; kk += 16) {
            uint32_t ah[4][4], al[4][4];
#pragma unroll
            for (int mt = 0; mt < 4; mt++) {
                int r = 64 * wm + 16 * mt + (lane & 15);
                int c = kk + (lane >> 4) * 8;
                ldsm4(ah[mt], sptr(&s.Ah[st][r][c]));
                ldsm4(al[mt], sptr(&s.Al[st][r][c]));
            }
#pragma unroll
            for (int np = 0; np < 2; np++) {
                uint32_t bh[4], bl[4];
                int r = 32 * wn + 16 * np + (lane & 7) + (lane >> 4) * 8;
                int c = kk + ((lane >> 3) & 1) * 8;
                ldsm4(bh, sptr(&s.Bh[st][r][c]));
                ldsm4(bl, sptr(&s.Bl[st][r][c]));
#pragma unroll
                for (int mt = 0; mt < 4; mt++) {
#pragma unroll
                    for (int h2 = 0; h2 < 2; h2++) {
                        float* cc = acc[mt][2 * np + h2];
                        mma_bf16(cc, ah[mt], bh[2 * h2], bh[2 * h2 + 1]);
                        mma_bf16(cc, ah[mt], bl[2 * h2], bl[2 * h2 + 1]);
                        mma_bf16(cc, al[mt], bh[2 * h2], bh[2 * h2 + 1]);
                    }
                }
            }
        }
        __syncthreads();
    }

    // Epilogue
#pragma unroll
    for (int mt = 0; mt < 4; mt++) {
#pragma unroll
        for (int nt = 0; nt < 4; nt++) {
            int gr = row0 + 64 * wm + 16 * mt + (lane >> 2);
            int gc = col0 + 32 * wn + 8 * nt + 2 * (lane & 3);
            const float* cc = acc[mt][nt];
            if (SPLIT_OUT) {
                uint32_t h, l;
                split_pair(cc[0], cc[1], h, l);
                *reinterpret_cast<uint32_t*>(&Ch[(size_t)gr * N + gc]) = h;
                *reinterpret_cast<uint32_t*>(&Cl[(size_t)gr * N + gc]) = l;
                split_pair(cc[2], cc[3], h, l);
                *reinterpret_cast<uint32_t*>(&Ch[(size_t)(gr + 8) * N + gc]) = h;
                *reinterpret_cast<uint32_t*>(&Cl[(size_t)(gr + 8) * N + gc]) = l;
            } else {
                float b0 = bias[gc], b1 = bias[gc + 1];
                *reinterpret_cast<float2*>(&Cf[(size_t)gr * N + gc]) =
                    make_float2(cc[0] + b0, cc[1] + b1);
                *reinterpret_cast<float2*>(&Cf[(size_t)(gr + 8) * N + gc]) =
                    make_float2(cc[2] + b0, cc[3] + b1);
            }
        }
    }
}

// ---------------------------------------------------------------------------
// Fused quadratic-ReLU attention, tensor cores + cp.async double buffering.
// ---------------------------------------------------------------------------
struct AttnSmem {
    __nv_bfloat16 Qh[128][72], Ql[128][72];
    __nv_bfloat16 Kh[2][128][72], Kl[2][128][72];
    __nv_bfloat16 Vh[2][128][72], Vl[2][128][72];
};

__device__ __forceinline__ void load_tile72_async(
    __nv_bfloat16 (*dst)[72], const __nv_bfloat16* __restrict__ src, int tid)
{
#pragma unroll
    for (int l = 0; l < 4; l++) {
        int idx = tid + 256 * l;      // 0..1023 16B slots
        int r = idx >> 3, p = idx & 7;
        cp16(&dst[r][p * 8], &src[(size_t)r * QKV_N + p * 8]);
    }
}

__global__ void __launch_bounds__(256, 1)
attn_mma(const __nv_bfloat16* __restrict__ qkv_hi,
         const __nv_bfloat16* __restrict__ qkv_lo,
         const float* __restrict__ alpha,
         const float* __restrict__ beta,
         const float* __restrict__ gamma,
         __nv_bfloat16* __restrict__ att_hi,
         __nv_bfloat16* __restrict__ att_lo)
{
    AttnSmem& s = *reinterpret_cast<AttnSmem*>(smem_raw);
    const int tid  = threadIdx.x;
    const int lane = tid & 31;
    const int w    = tid >> 5;
    const int qt   = blockIdx.x;
    const int h    = blockIdx.y;
    const int b    = blockIdx.z;
    const int q0   = qt * 128;

    const float av = alpha[h], bv = beta[h], gv = gamma[h];

    const size_t base = (size_t)(b * SEQ) * QKV_N + h * HD;

    // Group 0: Q tile + first K/V stage
    load_tile72_async(s.Qh, qkv_hi + base + (size_t)q0 * QKV_N, tid);
    load_tile72_async(s.Ql, qkv_lo + base + (size_t)q0 * QKV_N, tid);
    load_tile72_async(s.Kh[0], qkv_hi + base + DIM,     tid);
    load_tile72_async(s.Kl[0], qkv_lo + base + DIM,     tid);
    load_tile72_async(s.Vh[0], qkv_hi + base + 2 * DIM, tid);
    load_tile72_async(s.Vl[0], qkv_lo + base + 2 * DIM, tid);
    cp_commit();

    uint32_t qh[4][4], ql[4][4];
    float O[8][4];
#pragma unroll
    for (int j = 0; j < 8; j++)
#pragma unroll
        for (int q = 0; q < 4; q++) O[j][q] = 0.f;
    float rsum0 = 0.f, rsum1 = 0.f;

    for (int kt = 0; kt < SEQ / 128; kt++) {
        const int st = kt & 1;
        if (kt + 1 < SEQ / 128) {
            const size_t koff = base + (size_t)((kt + 1) * 128) * QKV_N;
            load_tile72_async(s.Kh[st ^ 1], qkv_hi + koff + DIM,     tid);
            load_tile72_async(s.Kl[st ^ 1], qkv_lo + koff + DIM,     tid);
            load_tile72_async(s.Vh[st ^ 1], qkv_hi + koff + 2 * DIM, tid);
            load_tile72_async(s.Vl[st ^ 1], qkv_lo + koff + 2 * DIM, tid);
            cp_commit();
            cp_wait<1>();
        } else {
            cp_wait<0>();
        }
        __syncthreads();

        if (kt == 0) {
            // Q fragments (persist across key tiles)
#pragma unroll
            for (int kc = 0; kc < 4; kc++) {
                int r = 16 * w + (lane & 15);
                int c = 16 * kc + (lane >> 4) * 8;
                ldsm4(qh[kc], sptr(&s.Qh[r][c]));
                ldsm4(ql[kc], sptr(&s.Ql[r][c]));
            }
        }

        // ---- Phase 1: S = Q K^T ----
        float S[16][4];
#pragma unroll
        for (int j = 0; j < 16; j++)
#pragma unroll
            for (int q = 0; q < 4; q++) S[j][q] = 0.f;

#pragma unroll
        for (int kc = 0; kc < 4; kc++) {
#pragma unroll
            for (int np = 0; np < 8; np++) {
                uint32_t kh[4], kl[4];
                int r = 16 * np + (lane & 7) + (lane >> 4) * 8;
                int c = 16 * kc + ((lane >> 3) & 1) * 8;
                ldsm4(kh, sptr(&s.Kh[st][r][c]));
                ldsm4(kl, sptr(&s.Kl[st][r][c]));
                mma_bf16(S[2 * np + 0], qh[kc], kh[0], kh[1]);
                mma_bf16(S[2 * np + 0], qh[kc], kl[0], kl[1]);
                mma_bf16(S[2 * np + 0], ql[kc], kh[0], kh[1]);
                mma_bf16(S[2 * np + 1], qh[kc], kh[2], kh[3]);
                mma_bf16(S[2 * np + 1], qh[kc], kl[2], kl[3]);
                mma_bf16(S[2 * np + 1], ql[kc], kh[2], kh[3]);
            }
        }

        // ---- f(z) = relu(a z^2 + b z + g), row-sum partials ----
#pragma unroll
        for (int j = 0; j < 16; j++) {
#pragma unroll
            for (int q = 0; q < 4; q++) {
                float z = S[j][q] * ATT_SCALE;
                float p = fmaf(fmaf(av, z, bv), z, gv);
                S[j][q] = fmaxf(p, 0.f);
            }
            rsum0 += S[j][0] + S[j][1];
            rsum1 += S[j][2] + S[j][3];
        }

        // ---- Phase 2: O += P V ----
#pragma unroll
        for (int c8 = 0; c8 < 8; c8++) {
            uint32_t ph[4], pl[4];
            split_pair(S[2 * c8][0],     S[2 * c8][1],     ph[0], pl[0]);
            split_pair(S[2 * c8][2],     S[2 * c8][3],     ph[1], pl[1]);
            split_pair(S[2 * c8 + 1][0], S[2 * c8 + 1][1], ph[2], pl[2]);
            split_pair(S[2 * c8 + 1][2], S[2 * c8 + 1][3], ph[3], pl[3]);
#pragma unroll
            for (int ep = 0; ep < 4; ep++) {
                uint32_t vh[4], vl[4];
                int r = 16 * c8 + (lane & 7) + ((lane >> 3) & 1) * 8;
                int c = 16 * ep + (lane >> 4) * 8;
                ldsm4t(vh, sptr(&s.Vh[st][r][c]));
                ldsm4t(vl, sptr(&s.Vl[st][r][c]));
                mma_bf16(O[2 * ep + 0], ph, vh[0], vh[1]);
                mma_bf16(O[2 * ep + 0], ph, vl[0], vl[1]);
                mma_bf16(O[2 * ep + 0], pl, vh[0], vh[1]);
                mma_bf16(O[2 * ep + 1], ph, vh[2], vh[3]);
                mma_bf16(O[2 * ep + 1], ph, vl[2], vl[3]);
                mma_bf16(O[2 * ep + 1], pl, vh[2], vh[3]);
            }
        }
        __syncthreads();
    }

    // Row sums: reduce across the 4 lanes sharing each row
    rsum0 += __shfl_xor_sync(0xffffffffu, rsum0, 1);
    rsum0 += __shfl_xor_sync(0xffffffffu, rsum0, 2);
    rsum1 += __shfl_xor_sync(0xffffffffu, rsum1, 1);
    rsum1 += __shfl_xor_sync(0xffffffffu, rsum1, 2);
    const float inv0 = 1.f / (rsum0 + 1e-6f);
    const float inv1 = 1.f / (rsum1 + 1e-6f);

    const int r0 = b * SEQ + q0 + 16 * w + (lane >> 2);
#pragma unroll
    for (int j = 0; j < 8; j++) {
        int ce = h * HD + 8 * j + 2 * (lane & 3);
        uint32_t hh, ll;
        split_pair(O[j][0] * inv0, O[j][1] * inv0, hh, ll);
        *reinterpret_cast<uint32_t*>(&att_hi[(size_t)r0 * DIM + ce]) = hh;
        *reinterpret_cast<uint32_t*>(&att_lo[(size_t)r0 * DIM + ce]) = ll;
        split_pair(O[j][2] * inv1, O[j][3] * inv1, hh, ll);
        *reinterpret_cast<uint32_t*>(&att_hi[(size_t)(r0 + 8) * DIM + ce]) = hh;
        *reinterpret_cast<uint32_t*>(&att_lo[(size_t)(r0 + 8) * DIM + ce]) = ll;
    }
}

// ---------------------------------------------------------------------------
// Launch
// ---------------------------------------------------------------------------
extern "C" void kernel_launch(void* const* d_in, const int* in_sizes, int n_in,
                              void* d_out, int out_size)
{
    const float* x      = (const float*)d_in[0];
    const float* w_qkv  = (const float*)d_in[1];
    const float* w_proj = (const float*)d_in[2];
    const float* b_proj = (const float*)d_in[3];
    const float* alpha  = (const float*)d_in[4];
    const float* beta   = (const float*)d_in[5];
    const float* gamma  = (const float*)d_in[6];
    float* out = (float*)d_out;

    __nv_bfloat16 *xh, *xl, *wqh, *wql, *wph, *wpl, *qh, *ql, *ah, *al;
    cudaGetSymbolAddress((void**)&xh,  g_x_hi);
    cudaGetSymbolAddress((void**)&xl,  g_x_lo);
    cudaGetSymbolAddress((void**)&wqh, g_wqkv_hi);
    cudaGetSymbolAddress((void**)&wql, g_wqkv_lo);
    cudaGetSymbolAddress((void**)&wph, g_wproj_hi);
    cudaGetSymbolAddress((void**)&wpl, g_wproj_lo);
    cudaGetSymbolAddress((void**)&qh,  g_qkv_hi);
    cudaGetSymbolAddress((void**)&ql,  g_qkv_lo);
    cudaGetSymbolAddress((void**)&ah,  g_att_hi);
    cudaGetSymbolAddress((void**)&al,  g_att_lo);

    cudaFuncSetAttribute(gemm_bf16s<true>,
                         cudaFuncAttributeMaxDynamicSharedMemorySize,
                         (int)sizeof(GemmSmem));
    cudaFuncSetAttribute(gemm_bf16s<false>,
                         cudaFuncAttributeMaxDynamicSharedMemorySize,
                         (int)sizeof(GemmSmem));
    cudaFuncSetAttribute(attn_mma,
                         cudaFuncAttributeMaxDynamicSharedMemorySize,
                         (int)sizeof(AttnSmem));

    // 0) split fp32 inputs into bf16 hi/lo planes
    {
        int n4 = M_TOT * DIM / 4;
        split_planes<<<(n4 + 255) / 256, 256>>>((const float4*)x, (uint2*)xh, (uint2*)xl, n4);
        n4 = QKV_N * DIM / 4;
        split_planes<<<(n4 + 255) / 256, 256>>>((const float4*)w_qkv, (uint2*)wqh, (uint2*)wql, n4);
        n4 = DIM * DIM / 4;
        split_planes<<<(n4 + 255) / 256, 256>>>((const float4*)w_proj, (uint2*)wph, (uint2*)wpl, n4);
    }

    // 1) QKV projection -> split planes
    {
        dim3 grid(QKV_N / 128, M_TOT / 128);
        gemm_bf16s<true><<<grid, 256, sizeof(GemmSmem)>>>(
            xh, xl, wqh, wql, nullptr, qh, ql, nullptr, M_TOT, QKV_N, DIM);
    }

    // 2) Fused quadratic attention -> split planes
    {
        dim3 grid(SEQ / 128, NH, BB);
        attn_mma<<<grid, 256, sizeof(AttnSmem)>>>(qh, ql, alpha, beta, gamma, ah, al);
    }

    // 3) Output projection + bias -> fp32 out
    {
        dim3 grid(DIM / 128, M_TOT / 128);
        gemm_bf16s<false><<<grid, 256, sizeof(GemmSmem)>>>(
            ah, al, wph, wpl, b_proj, nullptr, nullptr, out, M_TOT, DIM, DIM);
    }
}

// round 5
// speedup vs baseline: 3.0533x; 1.1890x over previous
#include <cuda_runtime.h>
#include <cuda_fp16.h>
#include <cstdint>
#include <cstddef>

#define DIM      768
#define NH       12
#define HD       64
#define BB       8
#define SEQ      1024
#define M_TOT    (BB * SEQ)          // 8192
#define QKV_N    (3 * DIM)           // 2304
#define ATT_SCALE 0.125f
#define QB       256                 // q rows per attention CTA

// ---------------------------------------------------------------------------
// Scratch planes (fp16 hi/lo splits). Device globals: allocation-free.
// ---------------------------------------------------------------------------
__device__ __half g_x_hi[(size_t)M_TOT * DIM];
__device__ __half g_x_lo[(size_t)M_TOT * DIM];
__device__ __half g_wqkv_hi[(size_t)QKV_N * DIM];
__device__ __half g_wqkv_lo[(size_t)QKV_N * DIM];
__device__ __half g_wproj_hi[(size_t)DIM * DIM];
__device__ __half g_qkv_hi[(size_t)M_TOT * QKV_N];
__device__ __half g_qkv_lo[(size_t)M_TOT * QKV_N];
__device__ __half g_att_hi[(size_t)M_TOT * DIM];
__device__ __half g_att_lo[(size_t)M_TOT * DIM];

// ---------------------------------------------------------------------------
// Helpers
// ---------------------------------------------------------------------------
__device__ __forceinline__ uint32_t sptr(const void* p) {
    return (uint32_t)__cvta_generic_to_shared(p);
}
__device__ __forceinline__ void cp16(void* dst, const void* src) {
    asm volatile("cp.async.cg.shared.global [%0], [%1], 16;"
                 :: "r"(sptr(dst)), "l"(src));
}
__device__ __forceinline__ void cp_commit() {
    asm volatile("cp.async.commit_group;");
}
template<int N>
__device__ __forceinline__ void cp_wait() {
    asm volatile("cp.async.wait_group %0;" :: "n"(N));
}
__device__ __forceinline__ void ldsm4(uint32_t r[4], uint32_t a) {
    asm volatile("ldmatrix.sync.aligned.m8n8.x4.shared.b16 {%0,%1,%2,%3}, [%4];"
                 : "=r"(r[0]), "=r"(r[1]), "=r"(r[2]), "=r"(r[3]) : "r"(a));
}
__device__ __forceinline__ void ldsm4t(uint32_t r[4], uint32_t a) {
    asm volatile("ldmatrix.sync.aligned.m8n8.x4.trans.shared.b16 {%0,%1,%2,%3}, [%4];"
                 : "=r"(r[0]), "=r"(r[1]), "=r"(r[2]), "=r"(r[3]) : "r"(a));
}
__device__ __forceinline__ void mma_f16(float c[4], const uint32_t a[4],
                                        uint32_t b0, uint32_t b1) {
    asm volatile(
        "mma.sync.aligned.m16n8k16.row.col.f32.f16.f16.f32 "
        "{%0,%1,%2,%3},{%4,%5,%6,%7},{%8,%9},{%0,%1,%2,%3};"
        : "+f"(c[0]), "+f"(c[1]), "+f"(c[2]), "+f"(c[3])
        : "r"(a[0]), "r"(a[1]), "r"(a[2]), "r"(a[3]), "r"(b0), "r"(b1));
}
__device__ __forceinline__ uint32_t pack_h(float a, float b) {
    __half2 t = __floats2half2_rn(a, b);
    return *reinterpret_cast<uint32_t*>(&t);
}
__device__ __forceinline__ void split_pair_h(float x, float y,
                                             uint32_t& hi, uint32_t& lo) {
    __half hx = __float2half_rn(x), hy = __float2half_rn(y);
    hi = (uint32_t)__half_as_ushort(hx) | ((uint32_t)__half_as_ushort(hy) << 16);
    lo = pack_h(x - __half2float(hx), y - __half2float(hy));
}

// ---------------------------------------------------------------------------
// fp32 -> fp16 hi/lo plane conversion
// ---------------------------------------------------------------------------
__global__ void split_planes(const float4* __restrict__ in,
                             uint2* __restrict__ hi, uint2* __restrict__ lo,
                             int n4) {
    int i = blockIdx.x * blockDim.x + threadIdx.x;
    if (i >= n4) return;
    float4 v = in[i];
    uint32_t h0, l0, h1, l1;
    split_pair_h(v.x, v.y, h0, l0);
    split_pair_h(v.z, v.w, h1, l1);
    hi[i] = make_uint2(h0, h1);
    if (lo) lo[i] = make_uint2(l0, l1);
}

// ---------------------------------------------------------------------------
// Split-fp16 tensor-core GEMM with cp.async 2-stage pipeline.
// C[M,N] = A[M,K] * B[N,K]^T. 128x128 CTA tile, BK=32, 8 warps (2m x 4n).
// NMMA=3: ah*bh + ah*bl + al*bh (exact to ~2^-22)
// NMMA=2: ah*bh + al*bh        (B single fp16, ~2.8e-4)
// ---------------------------------------------------------------------------
struct GemmSmem {
    __half Ah[2][128][40], Al[2][128][40];
    __half Bh[2][128][40], Bl[2][128][40];
};
extern __shared__ __align__(1024) char smem_raw[];

template<int NMMA>
__device__ __forceinline__ void gemm_load_stage(
    GemmSmem& s, int st,
    const __half* __restrict__ Ah_g, const __half* __restrict__ Al_g,
    const __half* __restrict__ Bh_g, const __half* __restrict__ Bl_g,
    int row0, int col0, int K, int k0, int tid)
{
#pragma unroll
    for (int l = 0; l < 2; l++) {
        int idx = tid + 256 * l;        // 0..511
        int r = idx >> 2, p = idx & 3;  // row, 16B slot
        cp16(&s.Ah[st][r][p * 8], &Ah_g[(size_t)(row0 + r) * K + k0 + p * 8]);
        cp16(&s.Al[st][r][p * 8], &Al_g[(size_t)(row0 + r) * K + k0 + p * 8]);
        cp16(&s.Bh[st][r][p * 8], &Bh_g[(size_t)(col0 + r) * K + k0 + p * 8]);
        if (NMMA == 3)
            cp16(&s.Bl[st][r][p * 8], &Bl_g[(size_t)(col0 + r) * K + k0 + p * 8]);
    }
}

template<bool SPLIT_OUT, int NMMA>
__global__ void __launch_bounds__(256, 2)
gemm_f16s(const __half* __restrict__ Ah_g,
          const __half* __restrict__ Al_g,
          const __half* __restrict__ Bh_g,
          const __half* __restrict__ Bl_g,
          const float* __restrict__ bias,
          __half* __restrict__ Ch,
          __half* __restrict__ Cl,
          float* __restrict__ Cf,
          int M, int N, int K)
{
    GemmSmem& s = *reinterpret_cast<GemmSmem*>(smem_raw);

    const int tid  = threadIdx.x;
    const int lane = tid & 31;
    const int w    = tid >> 5;
    const int wm   = w & 1;
    const int wn   = w >> 1;
    const int row0 = blockIdx.y * 128;
    const int col0 = blockIdx.x * 128;

    float acc[4][4][4];
#pragma unroll
    for (int a = 0; a < 4; a++)
#pragma unroll
        for (int b = 0; b < 4; b++)
#pragma unroll
            for (int c = 0; c < 4; c++) acc[a][b][c] = 0.f;

    const int nk = K / 32;
    gemm_load_stage<NMMA>(s, 0, Ah_g, Al_g, Bh_g, Bl_g, row0, col0, K, 0, tid);
    cp_commit();

    for (int i = 0; i < nk; i++) {
        const int st = i & 1;
        if (i + 1 < nk) {
            gemm_load_stage<NMMA>(s, st ^ 1, Ah_g, Al_g, Bh_g, Bl_g,
                                  row0, col0, K, (i + 1) * 32, tid);
            cp_commit();
            cp_wait<1>();
        } else {
            cp_wait<0>();
        }
        __syncthreads();

#pragma unroll
        for (int kk = 0; kk < 32; kk += 16) {
            uint32_t ah[4][4], al[4][4];
#pragma unroll
            for (int mt = 0; mt < 4; mt++) {
                int r = 64 * wm + 16 * mt + (lane & 15);
                int c = kk + (lane >> 4) * 8;
                ldsm4(ah[mt], sptr(&s.Ah[st][r][c]));
                ldsm4(al[mt], sptr(&s.Al[st][r][c]));
            }
#pragma unroll
            for (int np = 0; np < 2; np++) {
                uint32_t bh[4], bl[4];
                int r = 32 * wn + 16 * np + (lane & 7) + (lane >> 4) * 8;
                int c = kk + ((lane >> 3) & 1) * 8;
                ldsm4(bh, sptr(&s.Bh[st][r][c]));
                if (NMMA == 3) ldsm4(bl, sptr(&s.Bl[st][r][c]));
#pragma unroll
                for (int mt = 0; mt < 4; mt++) {
#pragma unroll
                    for (int h2 = 0; h2 < 2; h2++) {
                        float* cc = acc[mt][2 * np + h2];
                        mma_f16(cc, ah[mt], bh[2 * h2], bh[2 * h2 + 1]);
                        if (NMMA == 3)
                            mma_f16(cc, ah[mt], bl[2 * h2], bl[2 * h2 + 1]);
                        mma_f16(cc, al[mt], bh[2 * h2], bh[2 * h2 + 1]);
                    }
                }
            }
        }
        __syncthreads();
    }

    // Epilogue
#pragma unroll
    for (int mt = 0; mt < 4; mt++) {
#pragma unroll
        for (int nt = 0; nt < 4; nt++) {
            int gr = row0 + 64 * wm + 16 * mt + (lane >> 2);
            int gc = col0 + 32 * wn + 8 * nt + 2 * (lane & 3);
            const float* cc = acc[mt][nt];
            if (SPLIT_OUT) {
                uint32_t h, l;
                split_pair_h(cc[0], cc[1], h, l);
                *reinterpret_cast<uint32_t*>(&Ch[(size_t)gr * N + gc]) = h;
                *reinterpret_cast<uint32_t*>(&Cl[(size_t)gr * N + gc]) = l;
                split_pair_h(cc[2], cc[3], h, l);
                *reinterpret_cast<uint32_t*>(&Ch[(size_t)(gr + 8) * N + gc]) = h;
                *reinterpret_cast<uint32_t*>(&Cl[(size_t)(gr + 8) * N + gc]) = l;
            } else {
                float b0 = bias[gc], b1 = bias[gc + 1];
                *reinterpret_cast<float2*>(&Cf[(size_t)gr * N + gc]) =
                    make_float2(cc[0] + b0, cc[1] + b1);
                *reinterpret_cast<float2*>(&Cf[(size_t)(gr + 8) * N + gc]) =
                    make_float2(cc[2] + b0, cc[3] + b1);
            }
        }
    }
}

// ---------------------------------------------------------------------------
// Fused quadratic-ReLU attention.
// CTA = 256 q-rows x (head, batch). 8 warps; warp w owns rows 32w..32w+31
// as two 16-row groups. Q fragments loaded straight from global (no Q smem).
// S = QK^T in 3-MMA fp16-split; P, V single fp16 (1 MMA) for P*V.
// K/V tiles double-buffered via cp.async.
// ---------------------------------------------------------------------------
struct AttnSmem {
    __half Kh[2][128][72], Kl[2][128][72], Vh[2][128][72];
};

__device__ __forceinline__ void load_tile72_async(
    __half (*dst)[72], const __half* __restrict__ src, int tid)
{
#pragma unroll
    for (int l = 0; l < 4; l++) {
        int idx = tid + 256 * l;      // 0..1023 16B slots
        int r = idx >> 3, p = idx & 7;
        cp16(&dst[r][p * 8], &src[(size_t)r * QKV_N + p * 8]);
    }
}

__global__ void __launch_bounds__(256, 1)
attn_mma(const __half* __restrict__ qkv_hi,
         const __half* __restrict__ qkv_lo,
         const float* __restrict__ alpha,
         const float* __restrict__ beta,
         const float* __restrict__ gamma,
         __half* __restrict__ att_hi,
         __half* __restrict__ att_lo)
{
    AttnSmem& s = *reinterpret_cast<AttnSmem*>(smem_raw);
    const int tid  = threadIdx.x;
    const int lane = tid & 31;
    const int w    = tid >> 5;
    const int qt   = blockIdx.x;
    const int h    = blockIdx.y;
    const int b    = blockIdx.z;
    const int q0   = qt * QB;

    const float av = alpha[h], bv = beta[h], gv = gamma[h];
    const size_t base = (size_t)(b * SEQ) * QKV_N + h * HD;

    // Prefetch first K/V tile
    load_tile72_async(s.Kh[0], qkv_hi + base + DIM,     tid);
    load_tile72_async(s.Kl[0], qkv_lo + base + DIM,     tid);
    load_tile72_async(s.Vh[0], qkv_hi + base + 2 * DIM, tid);
    cp_commit();

    // Q fragments directly from global: mma A-frag layout per 16x16 k-tile.
    uint32_t qh[2][4][4], ql[2][4][4];
    {
        const int rb = b * SEQ + q0 + 32 * w + (lane >> 2);
        const int cb = h * HD + 2 * (lane & 3);
#pragma unroll
        for (int rg = 0; rg < 2; rg++) {
#pragma unroll
            for (int kc = 0; kc < 4; kc++) {
                size_t o00 = (size_t)(rb + 16 * rg) * QKV_N + cb + 16 * kc;
                size_t o10 = o00 + 8 * QKV_N;
                qh[rg][kc][0] = *reinterpret_cast<const uint32_t*>(&qkv_hi[o00]);
                qh[rg][kc][1] = *reinterpret_cast<const uint32_t*>(&qkv_hi[o10]);
                qh[rg][kc][2] = *reinterpret_cast<const uint32_t*>(&qkv_hi[o00 + 8]);
                qh[rg][kc][3] = *reinterpret_cast<const uint32_t*>(&qkv_hi[o10 + 8]);
                ql[rg][kc][0] = *reinterpret_cast<const uint32_t*>(&qkv_lo[o00]);
                ql[rg][kc][1] = *reinterpret_cast<const uint32_t*>(&qkv_lo[o10]);
                ql[rg][kc][2] = *reinterpret_cast<const uint32_t*>(&qkv_lo[o00 + 8]);
                ql[rg][kc][3] = *reinterpret_cast<const uint32_t*>(&qkv_lo[o10 + 8]);
            }
        }
    }

    float O[2][8][4];
#pragma unroll
    for (int rg = 0; rg < 2; rg++)
#pragma unroll
        for (int j = 0; j < 8; j++)
#pragma unroll
            for (int q = 0; q < 4; q++) O[rg][j][q] = 0.f;
    float rs[2][2] = {{0.f, 0.f}, {0.f, 0.f}};

    for (int kt = 0; kt < SEQ / 128; kt++) {
        const int st = kt & 1;
        if (kt + 1 < SEQ / 128) {
            const size_t koff = base + (size_t)((kt + 1) * 128) * QKV_N;
            load_tile72_async(s.Kh[st ^ 1], qkv_hi + koff + DIM,     tid);
            load_tile72_async(s.Kl[st ^ 1], qkv_lo + koff + DIM,     tid);
            load_tile72_async(s.Vh[st ^ 1], qkv_hi + koff + 2 * DIM, tid);
            cp_commit();
            cp_wait<1>();
        } else {
            cp_wait<0>();
        }
        __syncthreads();

#pragma unroll
        for (int rg = 0; rg < 2; rg++) {
            // ---- S = Q K^T (3-MMA split) ----
            float S[16][4];
#pragma unroll
            for (int j = 0; j < 16; j++)
#pragma unroll
                for (int q = 0; q < 4; q++) S[j][q] = 0.f;

#pragma unroll
            for (int kc = 0; kc < 4; kc++) {
#pragma unroll
                for (int np = 0; np < 8; np++) {
                    uint32_t kh[4], kl[4];
                    int r = 16 * np + (lane & 7) + (lane >> 4) * 8;
                    int c = 16 * kc + ((lane >> 3) & 1) * 8;
                    ldsm4(kh, sptr(&s.Kh[st][r][c]));
                    ldsm4(kl, sptr(&s.Kl[st][r][c]));
                    mma_f16(S[2 * np + 0], qh[rg][kc], kh[0], kh[1]);
                    mma_f16(S[2 * np + 0], qh[rg][kc], kl[0], kl[1]);
                    mma_f16(S[2 * np + 0], ql[rg][kc], kh[0], kh[1]);
                    mma_f16(S[2 * np + 1], qh[rg][kc], kh[2], kh[3]);
                    mma_f16(S[2 * np + 1], qh[rg][kc], kl[2], kl[3]);
                    mma_f16(S[2 * np + 1], ql[rg][kc], kh[2], kh[3]);
                }
            }

            // ---- f(z) = relu(a z^2 + b z + g), row-sum partials ----
#pragma unroll
            for (int j = 0; j < 16; j++) {
#pragma unroll
                for (int q = 0; q < 4; q++) {
                    float z = S[j][q] * ATT_SCALE;
                    float p = fmaf(fmaf(av, z, bv), z, gv);
                    S[j][q] = fmaxf(p, 0.f);
                }
                rs[rg][0] += S[j][0] + S[j][1];
                rs[rg][1] += S[j][2] + S[j][3];
            }

            // ---- O += P V (single fp16 plane, 1 MMA) ----
#pragma unroll
            for (int c8 = 0; c8 < 8; c8++) {
                uint32_t ph[4];
                ph[0] = pack_h(S[2 * c8][0],     S[2 * c8][1]);
                ph[1] = pack_h(S[2 * c8][2],     S[2 * c8][3]);
                ph[2] = pack_h(S[2 * c8 + 1][0], S[2 * c8 + 1][1]);
                ph[3] = pack_h(S[2 * c8 + 1][2], S[2 * c8 + 1][3]);
#pragma unroll
                for (int ep = 0; ep < 4; ep++) {
                    uint32_t vh[4];
                    int r = 16 * c8 + (lane & 7) + ((lane >> 3) & 1) * 8;
                    int c = 16 * ep + (lane >> 4) * 8;
                    ldsm4t(vh, sptr(&s.Vh[st][r][c]));
                    mma_f16(O[rg][2 * ep + 0], ph, vh[0], vh[1]);
                    mma_f16(O[rg][2 * ep + 1], ph, vh[2], vh[3]);
                }
            }
        }
        __syncthreads();
    }

    // Row sums: reduce across the 4 lanes sharing each row; write out.
#pragma unroll
    for (int rg = 0; rg < 2; rg++) {
        float r0 = rs[rg][0], r1 = rs[rg][1];
        r0 += __shfl_xor_sync(0xffffffffu, r0, 1);
        r0 += __shfl_xor_sync(0xffffffffu, r0, 2);
        r1 += __shfl_xor_sync(0xffffffffu, r1, 1);
        r1 += __shfl_xor_sync(0xffffffffu, r1, 2);
        const float inv0 = 1.f / (r0 + 1e-6f);
        const float inv1 = 1.f / (r1 + 1e-6f);

        const int row = b * SEQ + q0 + 32 * w + 16 * rg + (lane >> 2);
#pragma unroll
        for (int j = 0; j < 8; j++) {
            int ce = h * HD + 8 * j + 2 * (lane & 3);
            uint32_t hh, ll;
            split_pair_h(O[rg][j][0] * inv0, O[rg][j][1] * inv0, hh, ll);
            *reinterpret_cast<uint32_t*>(&att_hi[(size_t)row * DIM + ce]) = hh;
            *reinterpret_cast<uint32_t*>(&att_lo[(size_t)row * DIM + ce]) = ll;
            split_pair_h(O[rg][j][2] * inv1, O[rg][j][3] * inv1, hh, ll);
            *reinterpret_cast<uint32_t*>(&att_hi[(size_t)(row + 8) * DIM + ce]) = hh;
            *reinterpret_cast<uint32_t*>(&att_lo[(size_t)(row + 8) * DIM + ce]) = ll;
        }
    }
}

// ---------------------------------------------------------------------------
// Launch
// ---------------------------------------------------------------------------
extern "C" void kernel_launch(void* const* d_in, const int* in_sizes, int n_in,
                              void* d_out, int out_size)
{
    const float* x      = (const float*)d_in[0];
    const float* w_qkv  = (const float*)d_in[1];
    const float* w_proj = (const float*)d_in[2];
    const float* b_proj = (const float*)d_in[3];
    const float* alpha  = (const float*)d_in[4];
    const float* beta   = (const float*)d_in[5];
    const float* gamma  = (const float*)d_in[6];
    float* out = (float*)d_out;

    __half *xh, *xl, *wqh, *wql, *wph, *qh, *ql, *ah, *al;
    cudaGetSymbolAddress((void**)&xh,  g_x_hi);
    cudaGetSymbolAddress((void**)&xl,  g_x_lo);
    cudaGetSymbolAddress((void**)&wqh, g_wqkv_hi);
    cudaGetSymbolAddress((void**)&wql, g_wqkv_lo);
    cudaGetSymbolAddress((void**)&wph, g_wproj_hi);
    cudaGetSymbolAddress((void**)&qh,  g_qkv_hi);
    cudaGetSymbolAddress((void**)&ql,  g_qkv_lo);
    cudaGetSymbolAddress((void**)&ah,  g_att_hi);
    cudaGetSymbolAddress((void**)&al,  g_att_lo);

    cudaFuncSetAttribute((const void*)gemm_f16s<true, 3>,
                         cudaFuncAttributeMaxDynamicSharedMemorySize,
                         (int)sizeof(GemmSmem));
    cudaFuncSetAttribute((const void*)gemm_f16s<false, 2>,
                         cudaFuncAttributeMaxDynamicSharedMemorySize,
                         (int)sizeof(GemmSmem));
    cudaFuncSetAttribute((const void*)attn_mma,
                         cudaFuncAttributeMaxDynamicSharedMemorySize,
                         (int)sizeof(AttnSmem));

    // 0) split fp32 inputs into fp16 hi/lo planes
    {
        int n4 = M_TOT * DIM / 4;
        split_planes<<<(n4 + 255) / 256, 256>>>((const float4*)x,
                                                (uint2*)xh, (uint2*)xl, n4);
        n4 = QKV_N * DIM / 4;
        split_planes<<<(n4 + 255) / 256, 256>>>((const float4*)w_qkv,
                                                (uint2*)wqh, (uint2*)wql, n4);
        n4 = DIM * DIM / 4;
        split_planes<<<(n4 + 255) / 256, 256>>>((const float4*)w_proj,
                                                (uint2*)wph, nullptr, n4);
    }

    // 1) QKV projection (3-MMA split) -> split fp16 planes
    {
        dim3 grid(QKV_N / 128, M_TOT / 128);
        gemm_f16s<true, 3><<<grid, 256, sizeof(GemmSmem)>>>(
            xh, xl, wqh, wql, nullptr, qh, ql, nullptr, M_TOT, QKV_N, DIM);
    }

    // 2) Fused quadratic attention -> split fp16 planes
    {
        dim3 grid(SEQ / QB, NH, BB);
        attn_mma<<<grid, 256, sizeof(AttnSmem)>>>(qh, ql, alpha, beta, gamma,
                                                  ah, al);
    }

    // 3) Output projection + bias (2-MMA, B single fp16) -> fp32 out
    {
        dim3 grid(DIM / 128, M_TOT / 128);
        gemm_f16s<false, 2><<<grid, 256, sizeof(GemmSmem)>>>(
            ah, al, wph, nullptr, b_proj, nullptr, nullptr, out,
            M_TOT, DIM, DIM);
    }
}